// round 4
// baseline (speedup 1.0000x reference)
#include <cuda_runtime.h>
#include <math.h>

#define BATCH 8
#define SEQ   16
#define NH    16
#define HD    128
#define DIM   2048
#define DIM3  6144
#define CACHE 4096
#define TTOT  4112
#define NTOK  128
#define NSPL  8

#define KH_OFF (NTOK*DIM)
#define KH_ELEMS (BATCH*NH*TTOT*HD)
#define VH_OFF (KH_OFF + KH_ELEMS)

typedef unsigned long long u64;

__device__ float g_qkv[NTOK * DIM3];            // 3 MB
__device__ float g_ctx[NTOK * DIM];             // 1 MB
__device__ float g_part[4 * NTOK * DIM3];       // split-K partials
__device__ float g_pacc[BATCH*NH*NSPL*SEQ*HD];  // attn partial ctx
__device__ float g_pm[BATCH*NH*NSPL*SEQ];
__device__ float g_pl[BATCH*NH*NSPL*SEQ];

// ---------- packed f32x2 helpers (sm_103a) ----------
__device__ __forceinline__ u64 pk2(float lo, float hi) {
    u64 r; asm("mov.b64 %0, {%1, %2};" : "=l"(r) : "f"(lo), "f"(hi)); return r;
}
__device__ __forceinline__ void upk2(u64 v, float& lo, float& hi) {
    asm("mov.b64 {%0, %1}, %2;" : "=f"(lo), "=f"(hi) : "l"(v));
}
__device__ __forceinline__ u64 ffma2(u64 a, u64 b, u64 c) {
    u64 d; asm("fma.rn.f32x2 %0, %1, %2, %3;" : "=l"(d) : "l"(a), "l"(b), "l"(c)); return d;
}
__device__ __forceinline__ u64 fmul2(u64 a, u64 b) {
    u64 d; asm("mul.rn.f32x2 %0, %1, %2;" : "=l"(d) : "l"(a), "l"(b)); return d;
}

// ---------- split-K GEMM: Cpart[split][128][N] = A[128,Kslice] @ Bw[Kslice,N] ----------
template<int KSLICE>
__global__ void __launch_bounds__(256)
gemm_splitk(const float* __restrict__ A, const float* __restrict__ Bw,
            float* __restrict__ Cpart, int N)
{
    constexpr int BN = 64, BK = 16;
    __shared__ float As[BK][NTOK];
    __shared__ float Bs[BK][BN];
    int tid = threadIdx.x;
    int n0 = blockIdx.x * BN;
    int kbase = blockIdx.y * KSLICE;
    int K = gridDim.y * KSLICE;
    int tx = tid & 15, ty = tid >> 4;

    u64 acc[4][4];
    #pragma unroll
    for (int i = 0; i < 4; i++)
        #pragma unroll
        for (int j = 0; j < 4; j++) acc[i][j] = 0ULL;

    for (int k0 = kbase; k0 < kbase + KSLICE; k0 += BK) {
        #pragma unroll
        for (int j = 0; j < 2; j++) {
            int lin = tid + j * 256;
            int am = lin & 127, k4 = (lin >> 7) * 4;
            float4 av = *(const float4*)&A[am * K + k0 + k4];
            As[k4+0][am] = av.x; As[k4+1][am] = av.y;
            As[k4+2][am] = av.z; As[k4+3][am] = av.w;
        }
        {
            int bk = tid >> 4, bn = (tid & 15) * 4;
            *(float4*)&Bs[bk][bn] = *(const float4*)&Bw[(k0 + bk) * N + n0 + bn];
        }
        __syncthreads();
        #pragma unroll
        for (int k = 0; k < BK; k++) {
            ulonglong2 a01 = *(const ulonglong2*)&As[k][ty*8];
            ulonglong2 a23 = *(const ulonglong2*)&As[k][ty*8 + 4];
            float4 bf = *(const float4*)&Bs[k][tx*4];
            u64 b0 = pk2(bf.x, bf.x), b1 = pk2(bf.y, bf.y);
            u64 b2 = pk2(bf.z, bf.z), b3 = pk2(bf.w, bf.w);
            acc[0][0] = ffma2(a01.x, b0, acc[0][0]);
            acc[0][1] = ffma2(a01.x, b1, acc[0][1]);
            acc[0][2] = ffma2(a01.x, b2, acc[0][2]);
            acc[0][3] = ffma2(a01.x, b3, acc[0][3]);
            acc[1][0] = ffma2(a01.y, b0, acc[1][0]);
            acc[1][1] = ffma2(a01.y, b1, acc[1][1]);
            acc[1][2] = ffma2(a01.y, b2, acc[1][2]);
            acc[1][3] = ffma2(a01.y, b3, acc[1][3]);
            acc[2][0] = ffma2(a23.x, b0, acc[2][0]);
            acc[2][1] = ffma2(a23.x, b1, acc[2][1]);
            acc[2][2] = ffma2(a23.x, b2, acc[2][2]);
            acc[2][3] = ffma2(a23.x, b3, acc[2][3]);
            acc[3][0] = ffma2(a23.y, b0, acc[3][0]);
            acc[3][1] = ffma2(a23.y, b1, acc[3][1]);
            acc[3][2] = ffma2(a23.y, b2, acc[3][2]);
            acc[3][3] = ffma2(a23.y, b3, acc[3][3]);
        }
        __syncthreads();
    }
    float* cp = Cpart + (size_t)blockIdx.y * NTOK * N;
    #pragma unroll
    for (int mp = 0; mp < 4; mp++) {
        float lo[4], hi[4];
        #pragma unroll
        for (int j = 0; j < 4; j++) upk2(acc[mp][j], lo[j], hi[j]);
        int m = ty * 8 + mp * 2;
        float4 w0 = {lo[0], lo[1], lo[2], lo[3]};
        float4 w1 = {hi[0], hi[1], hi[2], hi[3]};
        *(float4*)&cp[(m+0) * N + n0 + tx*4] = w0;
        *(float4*)&cp[(m+1) * N + n0 + tx*4] = w1;
    }
}

// ---------- split-K reduce ----------
template<int NS>
__global__ void __launch_bounds__(256)
reduce_part(const float* __restrict__ Cpart, const float* __restrict__ bias,
            float* __restrict__ C, int N)
{
    int idx = blockIdx.x * 256 + threadIdx.x;
    int n4 = N / 4;
    int m = idx / n4, n = (idx % n4) * 4;
    float4 s = *(const float4*)&bias[n];
    #pragma unroll
    for (int sp = 0; sp < NS; sp++) {
        float4 p = *(const float4*)&Cpart[(size_t)sp * NTOK * N + m * N + n];
        s.x += p.x; s.y += p.y; s.z += p.z; s.w += p.w;
    }
    *(float4*)&C[m * N + n] = s;
}

// ---------- split-KV flash attention + KV-concat writeout ----------
// grid (NSPL, NH, BATCH), 256 thr = 16 queries x 16 d-groups.
// Register-prefetch double buffering; score retention (no sc[32] array);
// expf dedup via Ps smem (each lane computes only its 2 exps).
__global__ void __launch_bounds__(256)
attn_split(const float* __restrict__ kc, const float* __restrict__ vc,
           float* __restrict__ out)
{
    __shared__ float Kt[32][HD];
    __shared__ float Vt[32][HD];
    __shared__ float Ps[SEQ][32];
    int sp = blockIdx.x, h = blockIdx.y, b = blockIdx.z;
    int tid = threadIdx.x;
    int s = tid >> 4, dg = tid & 15;

    int tb = sp * 16;
    int te = (sp == NSPL - 1) ? 129 : tb + 16;

    const float* qbase = &g_qkv[(b*SEQ + s)*DIM3 + h*HD];
    ulonglong2 qa = *(const ulonglong2*)&qbase[4*dg];
    ulonglong2 qb = *(const ulonglong2*)&qbase[64 + 4*dg];
    u64 qp0 = qa.x, qp1 = qa.y, qp2 = qb.x, qp3 = qb.y;

    u64 ac0 = 0ULL, ac1 = 0ULL, ac2 = 0ULL, ac3 = 0ULL;
    float m_r = -INFINITY, l_r = 0.f;
    const float SCALE = 0.08838834764831845f;

    const float* kcb = &kc[(size_t)(b*NH + h) * CACHE * HD];
    const float* vcb = &vc[(size_t)(b*NH + h) * CACHE * HD];
    float* khout = &out[KH_OFF + (size_t)(b*NH + h) * TTOT * HD];
    float* vhout = &out[VH_OFF + (size_t)(b*NH + h) * TTOT * HD];

    float4 pk[4], pv[4];
    {
        int t0 = tb * 32;
        #pragma unroll
        for (int i = 0; i < 4; i++) {
            int idx = tid + i * 256;
            int r = idx >> 5, c = idx & 31;
            int t = t0 + r;
            if (t < TTOT) {
                if (t < CACHE) {
                    pk[i] = *(const float4*)&kcb[t*HD + c*4];
                    pv[i] = *(const float4*)&vcb[t*HD + c*4];
                } else {
                    int tok = b*SEQ + (t - CACHE);
                    pk[i] = *(const float4*)&g_qkv[tok*DIM3 +   DIM + h*HD + c*4];
                    pv[i] = *(const float4*)&g_qkv[tok*DIM3 + 2*DIM + h*HD + c*4];
                }
            }
        }
    }

    for (int tile = tb; tile < te; tile++) {
        int t0 = tile * 32;
        int rows = min(32, TTOT - t0);
        #pragma unroll
        for (int i = 0; i < 4; i++) {
            int idx = tid + i * 256;
            int r = idx >> 5, c = idx & 31;
            int t = t0 + r;
            if (r < rows) {
                *(float4*)&Kt[r][c*4] = pk[i];
                *(float4*)&Vt[r][c*4] = pv[i];
                *(float4*)&khout[t*HD + c*4] = pk[i];
                *(float4*)&vhout[t*HD + c*4] = pv[i];
            }
        }
        __syncthreads();

        if (tile + 1 < te) {
            int nt0 = (tile + 1) * 32;
            #pragma unroll
            for (int i = 0; i < 4; i++) {
                int idx = tid + i * 256;
                int r = idx >> 5, c = idx & 31;
                int t = nt0 + r;
                if (t < TTOT) {
                    if (t < CACHE) {
                        pk[i] = *(const float4*)&kcb[t*HD + c*4];
                        pv[i] = *(const float4*)&vcb[t*HD + c*4];
                    } else {
                        int tok = b*SEQ + (t - CACHE);
                        pk[i] = *(const float4*)&g_qkv[tok*DIM3 +   DIM + h*HD + c*4];
                        pv[i] = *(const float4*)&g_qkv[tok*DIM3 + 2*DIM + h*HD + c*4];
                    }
                }
            }
        }

        bool masked = (tile == 128);
        float s0 = 0.f, s1 = 0.f;       // retained scores for keys dg, dg+16
        float tmax = m_r;
        #pragma unroll
        for (int tt = 0; tt < 32; tt++) {
            ulonglong2 k0 = *(const ulonglong2*)&Kt[tt][4*dg];
            ulonglong2 k1 = *(const ulonglong2*)&Kt[tt][64 + 4*dg];
            u64 p2 = ffma2(qp0, k0.x, fmul2(qp1, k0.y));
            p2 = ffma2(qp2, k1.x, p2);
            p2 = ffma2(qp3, k1.y, p2);
            float lo, hi; upk2(p2, lo, hi);
            float part = lo + hi;
            part += __shfl_xor_sync(0xffffffffu, part, 1);
            part += __shfl_xor_sync(0xffffffffu, part, 2);
            part += __shfl_xor_sync(0xffffffffu, part, 4);
            part += __shfl_xor_sync(0xffffffffu, part, 8);
            float sc = part * SCALE;
            if (masked && (t0 + tt > CACHE + s)) sc = -INFINITY;
            tmax = fmaxf(tmax, sc);
            if (tt == dg)      s0 = sc;
            if (tt == dg + 16) s1 = sc;
        }

        float corr = __expf(m_r - tmax);
        m_r = tmax;
        float e0 = __expf(s0 - tmax);
        float e1 = __expf(s1 - tmax);
        Ps[s][dg]      = e0;
        Ps[s][dg + 16] = e1;
        float lsum = e0 + e1;
        lsum += __shfl_xor_sync(0xffffffffu, lsum, 1);
        lsum += __shfl_xor_sync(0xffffffffu, lsum, 2);
        lsum += __shfl_xor_sync(0xffffffffu, lsum, 4);
        lsum += __shfl_xor_sync(0xffffffffu, lsum, 8);
        l_r = l_r * corr + lsum;
        u64 corr2 = pk2(corr, corr);
        ac0 = fmul2(ac0, corr2); ac1 = fmul2(ac1, corr2);
        ac2 = fmul2(ac2, corr2); ac3 = fmul2(ac3, corr2);
        __syncwarp();

        #pragma unroll
        for (int tt = 0; tt < 32; tt++) {
            float p = Ps[s][tt];
            u64 p2 = pk2(p, p);
            ulonglong2 v0 = *(const ulonglong2*)&Vt[tt][4*dg];
            ulonglong2 v1 = *(const ulonglong2*)&Vt[tt][64 + 4*dg];
            ac0 = ffma2(p2, v0.x, ac0);
            ac1 = ffma2(p2, v0.y, ac1);
            ac2 = ffma2(p2, v1.x, ac2);
            ac3 = ffma2(p2, v1.y, ac3);
        }
        __syncthreads();
    }

    int pb = ((b*NH + h) * NSPL + sp) * SEQ + s;
    if (dg == 0) { g_pm[pb] = m_r; g_pl[pb] = l_r; }
    float o[8];
    upk2(ac0, o[0], o[1]); upk2(ac1, o[2], o[3]);
    upk2(ac2, o[4], o[5]); upk2(ac3, o[6], o[7]);
    float4 w0 = {o[0], o[1], o[2], o[3]};
    float4 w1 = {o[4], o[5], o[6], o[7]};
    *(float4*)&g_pacc[(size_t)pb * HD + 4*dg] = w0;
    *(float4*)&g_pacc[(size_t)pb * HD + 64 + 4*dg] = w1;
}

// ---------- combine split-KV partials -> g_ctx ----------
__global__ void __launch_bounds__(256)
attn_combine()
{
    int h = blockIdx.x, b = blockIdx.y;
    int tid = threadIdx.x;
    int s = tid >> 4, dg = tid & 15;
    int base = ((b*NH + h) * NSPL) * SEQ + s;

    float m[NSPL], l[NSPL];
    #pragma unroll
    for (int sp = 0; sp < NSPL; sp++) {
        m[sp] = g_pm[base + sp*SEQ];
        l[sp] = g_pl[base + sp*SEQ];
    }
    float M = m[0];
    #pragma unroll
    for (int sp = 1; sp < NSPL; sp++) M = fmaxf(M, m[sp]);
    float L = 0.f, w[NSPL];
    #pragma unroll
    for (int sp = 0; sp < NSPL; sp++) { w[sp] = __expf(m[sp] - M); L += w[sp] * l[sp]; }

    float o[8] = {0,0,0,0,0,0,0,0};
    #pragma unroll
    for (int sp = 0; sp < NSPL; sp++) {
        size_t pb = (size_t)(base + sp*SEQ) * HD;
        float4 a0 = *(const float4*)&g_pacc[pb + 4*dg];
        float4 a1 = *(const float4*)&g_pacc[pb + 64 + 4*dg];
        o[0] += w[sp]*a0.x; o[1] += w[sp]*a0.y; o[2] += w[sp]*a0.z; o[3] += w[sp]*a0.w;
        o[4] += w[sp]*a1.x; o[5] += w[sp]*a1.y; o[6] += w[sp]*a1.z; o[7] += w[sp]*a1.w;
    }
    float inv = 1.0f / L;
    float* cb = &g_ctx[(b*SEQ + s)*DIM + h*HD];
    float4 w0 = {o[0]*inv, o[1]*inv, o[2]*inv, o[3]*inv};
    float4 w1 = {o[4]*inv, o[5]*inv, o[6]*inv, o[7]*inv};
    *(float4*)&cb[4*dg] = w0;
    *(float4*)&cb[64 + 4*dg] = w1;
}

extern "C" void kernel_launch(void* const* d_in, const int* in_sizes, int n_in,
                              void* d_out, int out_size)
{
    const float* x      = (const float*)d_in[0];
    const float* kc     = (const float*)d_in[1];
    const float* vc     = (const float*)d_in[2];
    const float* W_attn = (const float*)d_in[3];
    const float* b_attn = (const float*)d_in[4];
    const float* W_proj = (const float*)d_in[5];
    const float* b_proj = (const float*)d_in[6];
    float* out = (float*)d_out;

    float *p_qkv, *p_ctx, *p_part;
    cudaGetSymbolAddress((void**)&p_qkv,  g_qkv);
    cudaGetSymbolAddress((void**)&p_ctx,  g_ctx);
    cudaGetSymbolAddress((void**)&p_part, g_part);

    gemm_splitk<512><<<dim3(DIM3/64, 4), 256>>>(x, W_attn, p_part, DIM3);
    reduce_part<4><<<(NTOK*DIM3/4)/256, 256>>>(p_part, b_attn, p_qkv, DIM3);
    attn_split<<<dim3(NSPL, NH, BATCH), 256>>>(kc, vc, out);
    attn_combine<<<dim3(NH, BATCH), 256>>>();
    gemm_splitk<256><<<dim3(DIM/64, 8), 256>>>(p_ctx, W_proj, p_part, DIM);
    reduce_part<8><<<(NTOK*DIM/4)/256, 256>>>(p_part, b_proj, out, DIM);
}

// round 5
// speedup vs baseline: 1.6767x; 1.6767x over previous
#include <cuda_runtime.h>
#include <math.h>

#define BATCH 8
#define SEQ   16
#define NH    16
#define HD    128
#define DIM   2048
#define DIM3  6144
#define CACHE 4096
#define TTOT  4112
#define NTOK  128
#define NSPL  4

#define KH_OFF (NTOK*DIM)
#define KH_ELEMS (BATCH*NH*TTOT*HD)
#define VH_OFF (KH_OFF + KH_ELEMS)

typedef unsigned long long u64;

__device__ float g_qkv[NTOK * DIM3];            // 3 MB
__device__ float g_ctx[NTOK * DIM];             // 1 MB
__device__ float g_part[4 * NTOK * DIM3];       // split-K partials
__device__ float g_pacc[BATCH*NH*NSPL*SEQ*HD];  // attn partial ctx
__device__ float g_pm[BATCH*NH*NSPL*SEQ];
__device__ float g_pl[BATCH*NH*NSPL*SEQ];

// ---------- packed f32x2 helpers (sm_103a) ----------
__device__ __forceinline__ u64 pk2(float lo, float hi) {
    u64 r; asm("mov.b64 %0, {%1, %2};" : "=l"(r) : "f"(lo), "f"(hi)); return r;
}
__device__ __forceinline__ void upk2(u64 v, float& lo, float& hi) {
    asm("mov.b64 {%0, %1}, %2;" : "=f"(lo), "=f"(hi) : "l"(v));
}
__device__ __forceinline__ u64 ffma2(u64 a, u64 b, u64 c) {
    u64 d; asm("fma.rn.f32x2 %0, %1, %2, %3;" : "=l"(d) : "l"(a), "l"(b), "l"(c)); return d;
}
__device__ __forceinline__ u64 fmul2(u64 a, u64 b) {
    u64 d; asm("mul.rn.f32x2 %0, %1, %2;" : "=l"(d) : "l"(a), "l"(b)); return d;
}

// ---------- butterfly-transpose reduce: 16 partials (one per key) spread over
// 16 lanes; 15 shuffles total; lane dg returns the full sum for key dg. ----------
__device__ __forceinline__ float bfly16(const float p[16], int dg) {
    const unsigned FULL = 0xffffffffu;
    bool b3 = (dg & 8) != 0;
    float q8[8];
    #pragma unroll
    for (int i = 0; i < 8; i++) {
        float send = b3 ? p[i] : p[i+8];
        float recv = __shfl_xor_sync(FULL, send, 8);
        q8[i] = (b3 ? p[i+8] : p[i]) + recv;
    }
    bool b2 = (dg & 4) != 0;
    float q4[4];
    #pragma unroll
    for (int i = 0; i < 4; i++) {
        float send = b2 ? q8[i] : q8[i+4];
        float recv = __shfl_xor_sync(FULL, send, 4);
        q4[i] = (b2 ? q8[i+4] : q8[i]) + recv;
    }
    bool b1 = (dg & 2) != 0;
    float q2[2];
    #pragma unroll
    for (int i = 0; i < 2; i++) {
        float send = b1 ? q4[i] : q4[i+2];
        float recv = __shfl_xor_sync(FULL, send, 2);
        q2[i] = (b1 ? q4[i+2] : q4[i]) + recv;
    }
    bool b0 = (dg & 1) != 0;
    float send = b0 ? q2[0] : q2[1];
    float recv = __shfl_xor_sync(FULL, send, 1);
    return (b0 ? q2[1] : q2[0]) + recv;
}

// ---------- split-K GEMM: Cpart[split][128][N] = A[128,Kslice] @ Bw[Kslice,N] ----------
template<int KSLICE>
__global__ void __launch_bounds__(256)
gemm_splitk(const float* __restrict__ A, const float* __restrict__ Bw,
            float* __restrict__ Cpart, int N)
{
    constexpr int BN = 64, BK = 16;
    __shared__ float As[BK][NTOK];
    __shared__ float Bs[BK][BN];
    int tid = threadIdx.x;
    int n0 = blockIdx.x * BN;
    int kbase = blockIdx.y * KSLICE;
    int K = gridDim.y * KSLICE;
    int tx = tid & 15, ty = tid >> 4;

    u64 acc[4][4];
    #pragma unroll
    for (int i = 0; i < 4; i++)
        #pragma unroll
        for (int j = 0; j < 4; j++) acc[i][j] = 0ULL;

    for (int k0 = kbase; k0 < kbase + KSLICE; k0 += BK) {
        #pragma unroll
        for (int j = 0; j < 2; j++) {
            int lin = tid + j * 256;
            int am = lin & 127, k4 = (lin >> 7) * 4;
            float4 av = *(const float4*)&A[am * K + k0 + k4];
            As[k4+0][am] = av.x; As[k4+1][am] = av.y;
            As[k4+2][am] = av.z; As[k4+3][am] = av.w;
        }
        {
            int bk = tid >> 4, bn = (tid & 15) * 4;
            *(float4*)&Bs[bk][bn] = *(const float4*)&Bw[(k0 + bk) * N + n0 + bn];
        }
        __syncthreads();
        #pragma unroll
        for (int k = 0; k < BK; k++) {
            ulonglong2 a01 = *(const ulonglong2*)&As[k][ty*8];
            ulonglong2 a23 = *(const ulonglong2*)&As[k][ty*8 + 4];
            float4 bf = *(const float4*)&Bs[k][tx*4];
            u64 b0 = pk2(bf.x, bf.x), b1 = pk2(bf.y, bf.y);
            u64 b2 = pk2(bf.z, bf.z), b3 = pk2(bf.w, bf.w);
            acc[0][0] = ffma2(a01.x, b0, acc[0][0]);
            acc[0][1] = ffma2(a01.x, b1, acc[0][1]);
            acc[0][2] = ffma2(a01.x, b2, acc[0][2]);
            acc[0][3] = ffma2(a01.x, b3, acc[0][3]);
            acc[1][0] = ffma2(a01.y, b0, acc[1][0]);
            acc[1][1] = ffma2(a01.y, b1, acc[1][1]);
            acc[1][2] = ffma2(a01.y, b2, acc[1][2]);
            acc[1][3] = ffma2(a01.y, b3, acc[1][3]);
            acc[2][0] = ffma2(a23.x, b0, acc[2][0]);
            acc[2][1] = ffma2(a23.x, b1, acc[2][1]);
            acc[2][2] = ffma2(a23.x, b2, acc[2][2]);
            acc[2][3] = ffma2(a23.x, b3, acc[2][3]);
            acc[3][0] = ffma2(a23.y, b0, acc[3][0]);
            acc[3][1] = ffma2(a23.y, b1, acc[3][1]);
            acc[3][2] = ffma2(a23.y, b2, acc[3][2]);
            acc[3][3] = ffma2(a23.y, b3, acc[3][3]);
        }
        __syncthreads();
    }
    float* cp = Cpart + (size_t)blockIdx.y * NTOK * N;
    #pragma unroll
    for (int mp = 0; mp < 4; mp++) {
        float lo[4], hi[4];
        #pragma unroll
        for (int j = 0; j < 4; j++) upk2(acc[mp][j], lo[j], hi[j]);
        int m = ty * 8 + mp * 2;
        float4 w0 = {lo[0], lo[1], lo[2], lo[3]};
        float4 w1 = {hi[0], hi[1], hi[2], hi[3]};
        *(float4*)&cp[(m+0) * N + n0 + tx*4] = w0;
        *(float4*)&cp[(m+1) * N + n0 + tx*4] = w1;
    }
}

// ---------- split-K reduce ----------
template<int NS>
__global__ void __launch_bounds__(256)
reduce_part(const float* __restrict__ Cpart, const float* __restrict__ bias,
            float* __restrict__ C, int N)
{
    int idx = blockIdx.x * 256 + threadIdx.x;
    int n4 = N / 4;
    int m = idx / n4, n = (idx % n4) * 4;
    float4 s = *(const float4*)&bias[n];
    #pragma unroll
    for (int sp = 0; sp < NS; sp++) {
        float4 p = *(const float4*)&Cpart[(size_t)sp * NTOK * N + m * N + n];
        s.x += p.x; s.y += p.y; s.z += p.z; s.w += p.w;
    }
    *(float4*)&C[m * N + n] = s;
}

// ---------- split-KV flash attention + KV-concat writeout ----------
// grid (NSPL, NH, BATCH), 256 thr = 16 queries x 16 d-groups.
// Butterfly-transpose score reduce (15 shfl / 16 keys), expf dedup (2/thread),
// register-prefetch double buffering of 32-key tiles.
__global__ void __launch_bounds__(256)
attn_split(const float* __restrict__ kc, const float* __restrict__ vc,
           float* __restrict__ out)
{
    __shared__ float Kt[32][HD];
    __shared__ float Vt[32][HD];
    __shared__ float Ps[SEQ][32];
    int sp = blockIdx.x, h = blockIdx.y, b = blockIdx.z;
    int tid = threadIdx.x;
    int s = tid >> 4, dg = tid & 15;

    int tb = sp * 32;
    int te = (sp == NSPL - 1) ? 129 : tb + 32;

    const float* qbase = &g_qkv[(b*SEQ + s)*DIM3 + h*HD];
    ulonglong2 qa = *(const ulonglong2*)&qbase[4*dg];
    ulonglong2 qb = *(const ulonglong2*)&qbase[64 + 4*dg];
    u64 qp0 = qa.x, qp1 = qa.y, qp2 = qb.x, qp3 = qb.y;

    u64 ac0 = 0ULL, ac1 = 0ULL, ac2 = 0ULL, ac3 = 0ULL;
    float m_r = -INFINITY, l_r = 0.f;
    const float SCALE = 0.08838834764831845f;

    const float* kcb = &kc[(size_t)(b*NH + h) * CACHE * HD];
    const float* vcb = &vc[(size_t)(b*NH + h) * CACHE * HD];
    float* khout = &out[KH_OFF + (size_t)(b*NH + h) * TTOT * HD];
    float* vhout = &out[VH_OFF + (size_t)(b*NH + h) * TTOT * HD];

    float4 pk[4], pv[4];
    {
        int t0 = tb * 32;
        #pragma unroll
        for (int i = 0; i < 4; i++) {
            int idx = tid + i * 256;
            int r = idx >> 5, c = idx & 31;
            int t = t0 + r;
            if (t < TTOT) {
                if (t < CACHE) {
                    pk[i] = *(const float4*)&kcb[t*HD + c*4];
                    pv[i] = *(const float4*)&vcb[t*HD + c*4];
                } else {
                    int tok = b*SEQ + (t - CACHE);
                    pk[i] = *(const float4*)&g_qkv[tok*DIM3 +   DIM + h*HD + c*4];
                    pv[i] = *(const float4*)&g_qkv[tok*DIM3 + 2*DIM + h*HD + c*4];
                }
            }
        }
    }

    for (int tile = tb; tile < te; tile++) {
        int t0 = tile * 32;
        int rows = min(32, TTOT - t0);
        #pragma unroll
        for (int i = 0; i < 4; i++) {
            int idx = tid + i * 256;
            int r = idx >> 5, c = idx & 31;
            int t = t0 + r;
            if (r < rows) {
                *(float4*)&Kt[r][c*4] = pk[i];
                *(float4*)&Vt[r][c*4] = pv[i];
                *(float4*)&khout[t*HD + c*4] = pk[i];
                *(float4*)&vhout[t*HD + c*4] = pv[i];
            }
        }
        __syncthreads();

        if (tile + 1 < te) {
            int nt0 = (tile + 1) * 32;
            #pragma unroll
            for (int i = 0; i < 4; i++) {
                int idx = tid + i * 256;
                int r = idx >> 5, c = idx & 31;
                int t = nt0 + r;
                if (t < TTOT) {
                    if (t < CACHE) {
                        pk[i] = *(const float4*)&kcb[t*HD + c*4];
                        pv[i] = *(const float4*)&vcb[t*HD + c*4];
                    } else {
                        int tok = b*SEQ + (t - CACHE);
                        pk[i] = *(const float4*)&g_qkv[tok*DIM3 +   DIM + h*HD + c*4];
                        pv[i] = *(const float4*)&g_qkv[tok*DIM3 + 2*DIM + h*HD + c*4];
                    }
                }
            }
        }

        // ---- score phase: 2 rounds x 16 keys, butterfly-transpose reduce ----
        float sc0, sc1;
        {
            float p[16];
            #pragma unroll
            for (int k = 0; k < 16; k++) {
                ulonglong2 k0 = *(const ulonglong2*)&Kt[k][4*dg];
                ulonglong2 k1 = *(const ulonglong2*)&Kt[k][64 + 4*dg];
                u64 p2 = ffma2(qp0, k0.x, fmul2(qp1, k0.y));
                p2 = ffma2(qp2, k1.x, p2);
                p2 = ffma2(qp3, k1.y, p2);
                float lo, hi; upk2(p2, lo, hi);
                p[k] = lo + hi;
            }
            sc0 = bfly16(p, dg) * SCALE;
            #pragma unroll
            for (int k = 0; k < 16; k++) {
                ulonglong2 k0 = *(const ulonglong2*)&Kt[16 + k][4*dg];
                ulonglong2 k1 = *(const ulonglong2*)&Kt[16 + k][64 + 4*dg];
                u64 p2 = ffma2(qp0, k0.x, fmul2(qp1, k0.y));
                p2 = ffma2(qp2, k1.x, p2);
                p2 = ffma2(qp3, k1.y, p2);
                float lo, hi; upk2(p2, lo, hi);
                p[k] = lo + hi;
            }
            sc1 = bfly16(p, dg) * SCALE;
        }
        if (tile == 128) {
            if (t0 + dg > CACHE + s)      sc0 = -INFINITY;
            if (t0 + 16 + dg > CACHE + s) sc1 = -INFINITY;
        }

        // ---- online softmax (max/sum over the 16-lane query group) ----
        float tmax = fmaxf(m_r, fmaxf(sc0, sc1));
        tmax = fmaxf(tmax, __shfl_xor_sync(0xffffffffu, tmax, 1));
        tmax = fmaxf(tmax, __shfl_xor_sync(0xffffffffu, tmax, 2));
        tmax = fmaxf(tmax, __shfl_xor_sync(0xffffffffu, tmax, 4));
        tmax = fmaxf(tmax, __shfl_xor_sync(0xffffffffu, tmax, 8));
        float corr = __expf(m_r - tmax);
        m_r = tmax;
        float e0 = __expf(sc0 - tmax);
        float e1 = __expf(sc1 - tmax);
        Ps[s][dg]      = e0;
        Ps[s][dg + 16] = e1;
        float lsum = e0 + e1;
        lsum += __shfl_xor_sync(0xffffffffu, lsum, 1);
        lsum += __shfl_xor_sync(0xffffffffu, lsum, 2);
        lsum += __shfl_xor_sync(0xffffffffu, lsum, 4);
        lsum += __shfl_xor_sync(0xffffffffu, lsum, 8);
        l_r = l_r * corr + lsum;
        u64 corr2 = pk2(corr, corr);
        ac0 = fmul2(ac0, corr2); ac1 = fmul2(ac1, corr2);
        ac2 = fmul2(ac2, corr2); ac3 = fmul2(ac3, corr2);
        __syncwarp();

        // ---- V accumulation (Ps broadcast via float4 reads) ----
        const float4* Pr = (const float4*)Ps[s];
        #pragma unroll
        for (int tq = 0; tq < 8; tq++) {
            float4 pv4 = Pr[tq];
            #pragma unroll
            for (int j = 0; j < 4; j++) {
                int tt = tq * 4 + j;
                float pj = (j == 0) ? pv4.x : (j == 1) ? pv4.y : (j == 2) ? pv4.z : pv4.w;
                u64 p2 = pk2(pj, pj);
                ulonglong2 v0 = *(const ulonglong2*)&Vt[tt][4*dg];
                ulonglong2 v1 = *(const ulonglong2*)&Vt[tt][64 + 4*dg];
                ac0 = ffma2(p2, v0.x, ac0);
                ac1 = ffma2(p2, v0.y, ac1);
                ac2 = ffma2(p2, v1.x, ac2);
                ac3 = ffma2(p2, v1.y, ac3);
            }
        }
        __syncthreads();
    }

    int pb = ((b*NH + h) * NSPL + sp) * SEQ + s;
    if (dg == 0) { g_pm[pb] = m_r; g_pl[pb] = l_r; }
    float o[8];
    upk2(ac0, o[0], o[1]); upk2(ac1, o[2], o[3]);
    upk2(ac2, o[4], o[5]); upk2(ac3, o[6], o[7]);
    float4 w0 = {o[0], o[1], o[2], o[3]};
    float4 w1 = {o[4], o[5], o[6], o[7]};
    *(float4*)&g_pacc[(size_t)pb * HD + 4*dg] = w0;
    *(float4*)&g_pacc[(size_t)pb * HD + 64 + 4*dg] = w1;
}

// ---------- combine split-KV partials -> g_ctx ----------
__global__ void __launch_bounds__(256)
attn_combine()
{
    int h = blockIdx.x, b = blockIdx.y;
    int tid = threadIdx.x;
    int s = tid >> 4, dg = tid & 15;
    int base = ((b*NH + h) * NSPL) * SEQ + s;

    float m[NSPL], l[NSPL];
    #pragma unroll
    for (int sp = 0; sp < NSPL; sp++) {
        m[sp] = g_pm[base + sp*SEQ];
        l[sp] = g_pl[base + sp*SEQ];
    }
    float M = m[0];
    #pragma unroll
    for (int sp = 1; sp < NSPL; sp++) M = fmaxf(M, m[sp]);
    float L = 0.f, w[NSPL];
    #pragma unroll
    for (int sp = 0; sp < NSPL; sp++) { w[sp] = __expf(m[sp] - M); L += w[sp] * l[sp]; }

    float o[8] = {0,0,0,0,0,0,0,0};
    #pragma unroll
    for (int sp = 0; sp < NSPL; sp++) {
        size_t pb = (size_t)(base + sp*SEQ) * HD;
        float4 a0 = *(const float4*)&g_pacc[pb + 4*dg];
        float4 a1 = *(const float4*)&g_pacc[pb + 64 + 4*dg];
        o[0] += w[sp]*a0.x; o[1] += w[sp]*a0.y; o[2] += w[sp]*a0.z; o[3] += w[sp]*a0.w;
        o[4] += w[sp]*a1.x; o[5] += w[sp]*a1.y; o[6] += w[sp]*a1.z; o[7] += w[sp]*a1.w;
    }
    float inv = 1.0f / L;
    float* cb = &g_ctx[(b*SEQ + s)*DIM + h*HD];
    float4 w0 = {o[0]*inv, o[1]*inv, o[2]*inv, o[3]*inv};
    float4 w1 = {o[4]*inv, o[5]*inv, o[6]*inv, o[7]*inv};
    *(float4*)&cb[4*dg] = w0;
    *(float4*)&cb[64 + 4*dg] = w1;
}

extern "C" void kernel_launch(void* const* d_in, const int* in_sizes, int n_in,
                              void* d_out, int out_size)
{
    const float* x      = (const float*)d_in[0];
    const float* kc     = (const float*)d_in[1];
    const float* vc     = (const float*)d_in[2];
    const float* W_attn = (const float*)d_in[3];
    const float* b_attn = (const float*)d_in[4];
    const float* W_proj = (const float*)d_in[5];
    const float* b_proj = (const float*)d_in[6];
    float* out = (float*)d_out;

    float *p_qkv, *p_ctx, *p_part;
    cudaGetSymbolAddress((void**)&p_qkv,  g_qkv);
    cudaGetSymbolAddress((void**)&p_ctx,  g_ctx);
    cudaGetSymbolAddress((void**)&p_part, g_part);

    gemm_splitk<512><<<dim3(DIM3/64, 4), 256>>>(x, W_attn, p_part, DIM3);
    reduce_part<4><<<(NTOK*DIM3/4)/256, 256>>>(p_part, b_attn, p_qkv, DIM3);
    attn_split<<<dim3(NSPL, NH, BATCH), 256>>>(kc, vc, out);
    attn_combine<<<dim3(NH, BATCH), 256>>>();
    gemm_splitk<256><<<dim3(DIM/64, 8), 256>>>(p_ctx, W_proj, p_part, DIM);
    reduce_part<8><<<(NTOK*DIM/4)/256, 256>>>(p_part, b_proj, out, DIM);
}

// round 7
// speedup vs baseline: 1.8362x; 1.0951x over previous
#include <cuda_runtime.h>
#include <stdint.h>
#include <math.h>

#define BATCH 8
#define SEQ   16
#define NH    16
#define HD    128
#define DIM   2048
#define DIM3  6144
#define CACHE 4096
#define TTOT  4112
#define NTOK  128
#define NSPL  4

#define KH_OFF (NTOK*DIM)
#define KH_ELEMS (BATCH*NH*TTOT*HD)
#define VH_OFF (KH_OFF + KH_ELEMS)

typedef unsigned long long u64;

__device__ float g_qkv[NTOK * DIM3];            // 3 MB
__device__ float g_ctx[NTOK * DIM];             // 1 MB
__device__ float g_part[4 * NTOK * DIM3];       // split-K partials
__device__ float g_pacc[BATCH*NH*NSPL*SEQ*HD];  // attn partial ctx
__device__ float g_pm[BATCH*NH*NSPL*SEQ];
__device__ float g_pl[BATCH*NH*NSPL*SEQ];

// ---------- packed f32x2 helpers (sm_103a) ----------
__device__ __forceinline__ u64 pk2(float lo, float hi) {
    u64 r; asm("mov.b64 %0, {%1, %2};" : "=l"(r) : "f"(lo), "f"(hi)); return r;
}
__device__ __forceinline__ void upk2(u64 v, float& lo, float& hi) {
    asm("mov.b64 {%0, %1}, %2;" : "=f"(lo), "=f"(hi) : "l"(v));
}
__device__ __forceinline__ u64 ffma2(u64 a, u64 b, u64 c) {
    u64 d; asm("fma.rn.f32x2 %0, %1, %2, %3;" : "=l"(d) : "l"(a), "l"(b), "l"(c)); return d;
}
__device__ __forceinline__ u64 fmul2(u64 a, u64 b) {
    u64 d; asm("mul.rn.f32x2 %0, %1, %2;" : "=l"(d) : "l"(a), "l"(b)); return d;
}

// ---------- cp.async helpers ----------
__device__ __forceinline__ void cpa16(void* smem_dst, const void* gmem_src) {
    unsigned int su = (unsigned int)__cvta_generic_to_shared(smem_dst);
    asm volatile("cp.async.cg.shared.global [%0], [%1], 16;" :: "r"(su), "l"(gmem_src));
}
#define CP_COMMIT() asm volatile("cp.async.commit_group;")
#define CP_WAIT(N)  asm volatile("cp.async.wait_group %0;" :: "n"(N))

// ---------- butterfly-transpose reduce ----------
__device__ __forceinline__ float bfly16(const float p[16], int dg) {
    const unsigned FULL = 0xffffffffu;
    bool b3 = (dg & 8) != 0;
    float q8[8];
    #pragma unroll
    for (int i = 0; i < 8; i++) {
        float send = b3 ? p[i] : p[i+8];
        float recv = __shfl_xor_sync(FULL, send, 8);
        q8[i] = (b3 ? p[i+8] : p[i]) + recv;
    }
    bool b2 = (dg & 4) != 0;
    float q4[4];
    #pragma unroll
    for (int i = 0; i < 4; i++) {
        float send = b2 ? q8[i] : q8[i+4];
        float recv = __shfl_xor_sync(FULL, send, 4);
        q4[i] = (b2 ? q8[i+4] : q8[i]) + recv;
    }
    bool b1 = (dg & 2) != 0;
    float q2[2];
    #pragma unroll
    for (int i = 0; i < 2; i++) {
        float send = b1 ? q4[i] : q4[i+2];
        float recv = __shfl_xor_sync(FULL, send, 2);
        q2[i] = (b1 ? q4[i+2] : q4[i]) + recv;
    }
    bool b0 = (dg & 1) != 0;
    float send = b0 ? q2[0] : q2[1];
    float recv = __shfl_xor_sync(FULL, send, 1);
    return (b0 ? q2[1] : q2[0]) + recv;
}

// ---------- split-K GEMM ----------
template<int KSLICE>
__global__ void __launch_bounds__(256)
gemm_splitk(const float* __restrict__ A, const float* __restrict__ Bw,
            float* __restrict__ Cpart, int N)
{
    constexpr int BN = 64, BK = 16;
    __shared__ float As[BK][NTOK];
    __shared__ float Bs[BK][BN];
    int tid = threadIdx.x;
    int n0 = blockIdx.x * BN;
    int kbase = blockIdx.y * KSLICE;
    int K = gridDim.y * KSLICE;
    int tx = tid & 15, ty = tid >> 4;

    u64 acc[4][4];
    #pragma unroll
    for (int i = 0; i < 4; i++)
        #pragma unroll
        for (int j = 0; j < 4; j++) acc[i][j] = 0ULL;

    for (int k0 = kbase; k0 < kbase + KSLICE; k0 += BK) {
        #pragma unroll
        for (int j = 0; j < 2; j++) {
            int lin = tid + j * 256;
            int am = lin & 127, k4 = (lin >> 7) * 4;
            float4 av = *(const float4*)&A[am * K + k0 + k4];
            As[k4+0][am] = av.x; As[k4+1][am] = av.y;
            As[k4+2][am] = av.z; As[k4+3][am] = av.w;
        }
        {
            int bk = tid >> 4, bn = (tid & 15) * 4;
            *(float4*)&Bs[bk][bn] = *(const float4*)&Bw[(k0 + bk) * N + n0 + bn];
        }
        __syncthreads();
        #pragma unroll
        for (int k = 0; k < BK; k++) {
            ulonglong2 a01 = *(const ulonglong2*)&As[k][ty*8];
            ulonglong2 a23 = *(const ulonglong2*)&As[k][ty*8 + 4];
            float4 bf = *(const float4*)&Bs[k][tx*4];
            u64 b0 = pk2(bf.x, bf.x), b1 = pk2(bf.y, bf.y);
            u64 b2 = pk2(bf.z, bf.z), b3 = pk2(bf.w, bf.w);
            acc[0][0] = ffma2(a01.x, b0, acc[0][0]);
            acc[0][1] = ffma2(a01.x, b1, acc[0][1]);
            acc[0][2] = ffma2(a01.x, b2, acc[0][2]);
            acc[0][3] = ffma2(a01.x, b3, acc[0][3]);
            acc[1][0] = ffma2(a01.y, b0, acc[1][0]);
            acc[1][1] = ffma2(a01.y, b1, acc[1][1]);
            acc[1][2] = ffma2(a01.y, b2, acc[1][2]);
            acc[1][3] = ffma2(a01.y, b3, acc[1][3]);
            acc[2][0] = ffma2(a23.x, b0, acc[2][0]);
            acc[2][1] = ffma2(a23.x, b1, acc[2][1]);
            acc[2][2] = ffma2(a23.x, b2, acc[2][2]);
            acc[2][3] = ffma2(a23.x, b3, acc[2][3]);
            acc[3][0] = ffma2(a23.y, b0, acc[3][0]);
            acc[3][1] = ffma2(a23.y, b1, acc[3][1]);
            acc[3][2] = ffma2(a23.y, b2, acc[3][2]);
            acc[3][3] = ffma2(a23.y, b3, acc[3][3]);
        }
        __syncthreads();
    }
    float* cp = Cpart + (size_t)blockIdx.y * NTOK * N;
    #pragma unroll
    for (int mp = 0; mp < 4; mp++) {
        float lo[4], hi[4];
        #pragma unroll
        for (int j = 0; j < 4; j++) upk2(acc[mp][j], lo[j], hi[j]);
        int m = ty * 8 + mp * 2;
        float4 w0 = {lo[0], lo[1], lo[2], lo[3]};
        float4 w1 = {hi[0], hi[1], hi[2], hi[3]};
        *(float4*)&cp[(m+0) * N + n0 + tx*4] = w0;
        *(float4*)&cp[(m+1) * N + n0 + tx*4] = w1;
    }
}

// ---------- split-K reduce ----------
template<int NS>
__global__ void __launch_bounds__(256)
reduce_part(const float* __restrict__ Cpart, const float* __restrict__ bias,
            float* __restrict__ C, int N)
{
    int idx = blockIdx.x * 256 + threadIdx.x;
    int n4 = N / 4;
    int m = idx / n4, n = (idx % n4) * 4;
    float4 s = *(const float4*)&bias[n];
    #pragma unroll
    for (int sp = 0; sp < NS; sp++) {
        float4 p = *(const float4*)&Cpart[(size_t)sp * NTOK * N + m * N + n];
        s.x += p.x; s.y += p.y; s.z += p.z; s.w += p.w;
    }
    *(float4*)&C[m * N + n] = s;
}

// dummy: shifts launch indices so ncu's fixed profile slot lands on attn_split
__global__ void dummy_k() {}

// ---------- split-KV flash attention, cp.async pipelined ----------
// Dyn smem: Kb[2][32][128] | Vb[32][128] | Ps[16][32]  = 51200 B.
// 256 thr = 16 q x 16 dg. K double-buffered, V single; copy-out from smem.
__global__ void __launch_bounds__(256, 4)
attn_split(const float* __restrict__ kc, const float* __restrict__ vc,
           float* __restrict__ out)
{
    extern __shared__ float sm[];
    float* Kb = sm;                  // 2*32*128 floats
    float* Vb = sm + 2*32*HD;        // 32*128
    float* Ps = sm + 3*32*HD;        // 16*32

    int sp = blockIdx.x, h = blockIdx.y, b = blockIdx.z;
    int tid = threadIdx.x;
    int s = tid >> 4, dg = tid & 15;
    int w8 = tid >> 5;               // copy rows: w8, w8+8, w8+16, w8+24
    int c4 = (tid & 31) * 4;         // copy col offset (floats)

    int tb = sp * 32;
    int te = (sp == NSPL - 1) ? 129 : tb + 32;

    const float* qbase = &g_qkv[(b*SEQ + s)*DIM3 + h*HD];
    ulonglong2 qa = *(const ulonglong2*)&qbase[4*dg];
    ulonglong2 qb = *(const ulonglong2*)&qbase[64 + 4*dg];
    u64 qp0 = qa.x, qp1 = qa.y, qp2 = qb.x, qp3 = qb.y;

    u64 ac0 = 0ULL, ac1 = 0ULL, ac2 = 0ULL, ac3 = 0ULL;
    float m_r = -INFINITY, l_r = 0.f;
    const float SCALE = 0.08838834764831845f;

    const float* kcb  = &kc[(size_t)(b*NH + h) * CACHE * HD];
    const float* vcb  = &vc[(size_t)(b*NH + h) * CACHE * HD];
    const float* qkvK = &g_qkv[(size_t)(b*SEQ)*DIM3 +   DIM + h*HD];
    const float* qkvV = &g_qkv[(size_t)(b*SEQ)*DIM3 + 2*DIM + h*HD];
    float* khout = &out[KH_OFF + (size_t)(b*NH + h) * TTOT * HD];
    float* vhout = &out[VH_OFF + (size_t)(b*NH + h) * TTOT * HD];

    // issue one K tile into buffer bsel
    auto issueK = [&](int tile, int bsel) {
        float* dst = Kb + bsel * 32 * HD;
        #pragma unroll
        for (int i = 0; i < 4; i++) {
            int rr = w8 + 8*i;
            int t = tile * 32 + rr;
            int tc = t < TTOT ? t : TTOT - 1;
            const float* src = (tc < CACHE) ? (kcb + (size_t)tc*HD + c4)
                                            : (qkvK + (size_t)(tc-CACHE)*DIM3 + c4);
            cpa16(dst + rr*HD + c4, src);
        }
    };
    auto issueV = [&](int tile) {
        #pragma unroll
        for (int i = 0; i < 4; i++) {
            int rr = w8 + 8*i;
            int t = tile * 32 + rr;
            int tc = t < TTOT ? t : TTOT - 1;
            const float* src = (tc < CACHE) ? (vcb + (size_t)tc*HD + c4)
                                            : (qkvV + (size_t)(tc-CACHE)*DIM3 + c4);
            cpa16(Vb + rr*HD + c4, src);
        }
    };

    // prologue: G0=K_tb, G1=V_tb, G2=K_{tb+1}
    issueK(tb, 0); CP_COMMIT();
    issueV(tb);    CP_COMMIT();
    if (tb + 1 < te) issueK(tb + 1, 1);
    CP_COMMIT();
    CP_WAIT(2);
    __syncthreads();                 // K_tb visible

    for (int tile = tb; tile < te; tile++) {
        int t0 = tile * 32;
        int buf = (tile - tb) & 1;
        const float* Kt = Kb + buf * 32 * HD;

        // ---- score phase (Kt ready) ----
        float sc0, sc1;
        {
            float p[16];
            #pragma unroll
            for (int k = 0; k < 16; k++) {
                ulonglong2 k0 = *(const ulonglong2*)&Kt[k*HD + 4*dg];
                ulonglong2 k1 = *(const ulonglong2*)&Kt[k*HD + 64 + 4*dg];
                u64 p2 = ffma2(qp0, k0.x, fmul2(qp1, k0.y));
                p2 = ffma2(qp2, k1.x, p2);
                p2 = ffma2(qp3, k1.y, p2);
                float lo, hi; upk2(p2, lo, hi);
                p[k] = lo + hi;
            }
            sc0 = bfly16(p, dg) * SCALE;
            #pragma unroll
            for (int k = 0; k < 16; k++) {
                ulonglong2 k0 = *(const ulonglong2*)&Kt[(16+k)*HD + 4*dg];
                ulonglong2 k1 = *(const ulonglong2*)&Kt[(16+k)*HD + 64 + 4*dg];
                u64 p2 = ffma2(qp0, k0.x, fmul2(qp1, k0.y));
                p2 = ffma2(qp2, k1.x, p2);
                p2 = ffma2(qp3, k1.y, p2);
                float lo, hi; upk2(p2, lo, hi);
                p[k] = lo + hi;
            }
            sc1 = bfly16(p, dg) * SCALE;
        }
        if (tile == 128) {
            if (t0 + dg > CACHE + s)      sc0 = -INFINITY;
            if (t0 + 16 + dg > CACHE + s) sc1 = -INFINITY;
        }

        // ---- wait V_i ----
        CP_WAIT(1);
        __syncthreads();

        // ---- online softmax ----
        float tmax = fmaxf(m_r, fmaxf(sc0, sc1));
        tmax = fmaxf(tmax, __shfl_xor_sync(0xffffffffu, tmax, 1));
        tmax = fmaxf(tmax, __shfl_xor_sync(0xffffffffu, tmax, 2));
        tmax = fmaxf(tmax, __shfl_xor_sync(0xffffffffu, tmax, 4));
        tmax = fmaxf(tmax, __shfl_xor_sync(0xffffffffu, tmax, 8));
        float corr = __expf(m_r - tmax);
        m_r = tmax;
        float e0 = __expf(sc0 - tmax);
        float e1 = __expf(sc1 - tmax);
        Ps[s*32 + dg]      = e0;
        Ps[s*32 + dg + 16] = e1;
        float lsum = e0 + e1;
        lsum += __shfl_xor_sync(0xffffffffu, lsum, 1);
        lsum += __shfl_xor_sync(0xffffffffu, lsum, 2);
        lsum += __shfl_xor_sync(0xffffffffu, lsum, 4);
        lsum += __shfl_xor_sync(0xffffffffu, lsum, 8);
        l_r = l_r * corr + lsum;
        u64 corr2 = pk2(corr, corr);
        ac0 = fmul2(ac0, corr2); ac1 = fmul2(ac1, corr2);
        ac2 = fmul2(ac2, corr2); ac3 = fmul2(ac3, corr2);
        __syncwarp();

        // ---- V accumulation ----
        const float4* Pr = (const float4*)(Ps + s*32);
        #pragma unroll
        for (int tq = 0; tq < 8; tq++) {
            float4 pv4 = Pr[tq];
            #pragma unroll
            for (int j = 0; j < 4; j++) {
                int tt = tq * 4 + j;
                float pj = (j == 0) ? pv4.x : (j == 1) ? pv4.y : (j == 2) ? pv4.z : pv4.w;
                u64 p2 = pk2(pj, pj);
                ulonglong2 v0 = *(const ulonglong2*)&Vb[tt*HD + 4*dg];
                ulonglong2 v1 = *(const ulonglong2*)&Vb[tt*HD + 64 + 4*dg];
                ac0 = ffma2(p2, v0.x, ac0);
                ac1 = ffma2(p2, v0.y, ac1);
                ac2 = ffma2(p2, v1.x, ac2);
                ac3 = ffma2(p2, v1.y, ac3);
            }
        }

        // ---- copy-out K_i, V_i from smem to kh/vh ----
        #pragma unroll
        for (int i = 0; i < 4; i++) {
            int rr = w8 + 8*i;
            int t = t0 + rr;
            if (t < TTOT) {
                float4 kv = *(const float4*)&Kt[rr*HD + c4];
                float4 vv = *(const float4*)&Vb[rr*HD + c4];
                *(float4*)&khout[(size_t)t*HD + c4] = kv;
                *(float4*)&vhout[(size_t)t*HD + c4] = vv;
            }
        }
        __syncthreads();             // Vb and Kt reads complete

        // ---- issue V_{i+1}, K_{i+2} ----
        if (tile + 1 < te) issueV(tile + 1);
        CP_COMMIT();
        if (tile + 2 < te) issueK(tile + 2, buf);
        CP_COMMIT();
        CP_WAIT(2);                  // K_{i+1} complete
        __syncthreads();
    }

    int pb = ((b*NH + h) * NSPL + sp) * SEQ + s;
    if (dg == 0) { g_pm[pb] = m_r; g_pl[pb] = l_r; }
    float o[8];
    upk2(ac0, o[0], o[1]); upk2(ac1, o[2], o[3]);
    upk2(ac2, o[4], o[5]); upk2(ac3, o[6], o[7]);
    float4 w0 = {o[0], o[1], o[2], o[3]};
    float4 w1 = {o[4], o[5], o[6], o[7]};
    *(float4*)&g_pacc[(size_t)pb * HD + 4*dg] = w0;
    *(float4*)&g_pacc[(size_t)pb * HD + 64 + 4*dg] = w1;
}

// ---------- combine split-KV partials -> g_ctx ----------
__global__ void __launch_bounds__(256)
attn_combine()
{
    int h = blockIdx.x, b = blockIdx.y;
    int tid = threadIdx.x;
    int s = tid >> 4, dg = tid & 15;
    int base = ((b*NH + h) * NSPL) * SEQ + s;

    float m[NSPL], l[NSPL];
    #pragma unroll
    for (int sp = 0; sp < NSPL; sp++) {
        m[sp] = g_pm[base + sp*SEQ];
        l[sp] = g_pl[base + sp*SEQ];
    }
    float M = m[0];
    #pragma unroll
    for (int sp = 1; sp < NSPL; sp++) M = fmaxf(M, m[sp]);
    float L = 0.f, w[NSPL];
    #pragma unroll
    for (int sp = 0; sp < NSPL; sp++) { w[sp] = __expf(m[sp] - M); L += w[sp] * l[sp]; }

    float o[8] = {0,0,0,0,0,0,0,0};
    #pragma unroll
    for (int sp = 0; sp < NSPL; sp++) {
        size_t pb = (size_t)(base + sp*SEQ) * HD;
        float4 a0 = *(const float4*)&g_pacc[pb + 4*dg];
        float4 a1 = *(const float4*)&g_pacc[pb + 64 + 4*dg];
        o[0] += w[sp]*a0.x; o[1] += w[sp]*a0.y; o[2] += w[sp]*a0.z; o[3] += w[sp]*a0.w;
        o[4] += w[sp]*a1.x; o[5] += w[sp]*a1.y; o[6] += w[sp]*a1.z; o[7] += w[sp]*a1.w;
    }
    float inv = 1.0f / L;
    float* cb = &g_ctx[(b*SEQ + s)*DIM + h*HD];
    float4 w0 = {o[0]*inv, o[1]*inv, o[2]*inv, o[3]*inv};
    float4 w1 = {o[4]*inv, o[5]*inv, o[6]*inv, o[7]*inv};
    *(float4*)&cb[4*dg] = w0;
    *(float4*)&cb[64 + 4*dg] = w1;
}

extern "C" void kernel_launch(void* const* d_in, const int* in_sizes, int n_in,
                              void* d_out, int out_size)
{
    const float* x      = (const float*)d_in[0];
    const float* kc     = (const float*)d_in[1];
    const float* vc     = (const float*)d_in[2];
    const float* W_attn = (const float*)d_in[3];
    const float* b_attn = (const float*)d_in[4];
    const float* W_proj = (const float*)d_in[5];
    const float* b_proj = (const float*)d_in[6];
    float* out = (float*)d_out;

    float *p_qkv, *p_ctx, *p_part;
    cudaGetSymbolAddress((void**)&p_qkv,  g_qkv);
    cudaGetSymbolAddress((void**)&p_ctx,  g_ctx);
    cudaGetSymbolAddress((void**)&p_part, g_part);

    const int ATTN_SMEM = (3*32*HD + SEQ*32) * 4;   // 51200 B
    cudaFuncSetAttribute(attn_split, cudaFuncAttributeMaxDynamicSharedMemorySize, ATTN_SMEM);

    gemm_splitk<512><<<dim3(DIM3/64, 4), 256>>>(x, W_attn, p_part, DIM3);        // #0
    reduce_part<4><<<(NTOK*DIM3/4)/256, 256>>>(p_part, b_attn, p_qkv, DIM3);     // #1
    dummy_k<<<1, 32>>>();                                                        // #2
    attn_split<<<dim3(NSPL, NH, BATCH), 256, ATTN_SMEM>>>(kc, vc, out);          // #3
    attn_combine<<<dim3(NH, BATCH), 256>>>();                                    // #4
    gemm_splitk<256><<<dim3(DIM/64, 8), 256>>>(p_ctx, W_proj, p_part, DIM);      // #5
    reduce_part<8><<<(NTOK*DIM/4)/256, 256>>>(p_part, b_proj, out, DIM);         // #6
}